// round 5
// baseline (speedup 1.0000x reference)
#include <cuda_runtime.h>
#include <cuda_bf16.h>
#include <stdint.h>

// ---------------------------------------------------------------------------
// Problem constants
// ---------------------------------------------------------------------------
#define BB     16384
#define DI     1024
#define DH     1024
#define KTOT   2048           // Di + Dh packed K
#define NROWS  4096           // 4*Dh gate rows (permuted)
#define TM     128
#define TN     128
#define KCH    32             // K elems per pipeline chunk
#define STAGES 4
#define THREADS 256
#define NKT    64             // single fused sweep: 2048/32
#define ROWB   80             // smem row stride bytes (32 bf16 = 64B + 16B pad)
#define TILE_BYTES  (128 * ROWB)              // 10240 per operand tile
#define STAGE_BYTES (4 * TILE_BYTES)          // Ah, Al, Bh, Bl
#define OFF_AL      (1 * TILE_BYTES)
#define OFF_BH      (2 * TILE_BYTES)
#define OFF_BL      (3 * TILE_BYTES)
#define SMEM_TOTAL  (STAGES * STAGE_BYTES)    // 163840

// ---------------------------------------------------------------------------
// Device scratch
// ---------------------------------------------------------------------------
__device__ __nv_bfloat16 g_Ah[(size_t)BB * KTOT];
__device__ __nv_bfloat16 g_Al[(size_t)BB * KTOT];
__device__ __nv_bfloat16 g_Bh[(size_t)NROWS * KTOT];
__device__ __nv_bfloat16 g_Bl[(size_t)NROWS * KTOT];

// ---------------------------------------------------------------------------
// PTX helpers (base-ISA only)
// ---------------------------------------------------------------------------
__device__ __forceinline__ uint32_t smem_u32(const void* p) {
    uint32_t a;
    asm("{ .reg .u64 t; cvta.to.shared.u64 t, %1; cvt.u32.u64 %0, t; }"
        : "=r"(a) : "l"(p));
    return a;
}

__device__ __forceinline__ void cp_async16(uint32_t so, const void* gp) {
    asm volatile("cp.async.cg.shared.global [%0], [%1], 16;" :: "r"(so), "l"(gp));
}
#define CP_COMMIT() asm volatile("cp.async.commit_group;" ::: "memory")
#define CP_WAIT2()  asm volatile("cp.async.wait_group 2;" ::: "memory")

#define LDSM_X4(R, ADDR)                                                      \
    asm volatile("ldmatrix.sync.aligned.m8n8.x4.shared.b16 {%0,%1,%2,%3}, [%4];" \
                 : "=r"((R)[0]), "=r"((R)[1]), "=r"((R)[2]), "=r"((R)[3])     \
                 : "r"(ADDR))

#define MMA16816(C, A, B0, B1)                                                \
    asm volatile("mma.sync.aligned.m16n8k16.row.col.f32.bf16.bf16.f32 "       \
                 "{%0,%1,%2,%3},{%4,%5,%6,%7},{%8,%9},{%0,%1,%2,%3};"         \
                 : "+f"((C)[0]), "+f"((C)[1]), "+f"((C)[2]), "+f"((C)[3])     \
                 : "r"((A)[0]), "r"((A)[1]), "r"((A)[2]), "r"((A)[3]),        \
                   "r"(B0), "r"(B1))

__device__ __forceinline__ float sigf(float x)   { return 1.0f / (1.0f + __expf(-x)); }
__device__ __forceinline__ float tanh_f(float x) { return 1.0f - 2.0f / (__expf(2.0f * x) + 1.0f); }

// ---------------------------------------------------------------------------
// Prep: pack fp32 inputs into bf16 hi/lo operands
// ---------------------------------------------------------------------------
__global__ void pack_A(const float* __restrict__ X, const float* __restrict__ h0) {
    size_t i4 = ((size_t)blockIdx.x * blockDim.x + threadIdx.x) * 4;
    int k = (int)(i4 & (KTOT - 1));
    size_t b = i4 >> 11;
    const float* src = (k < DI) ? (X + b * DI + k) : (h0 + b * DH + (k - DI));
    float4 v = *(const float4*)src;
    __nv_bfloat16 h0v = __float2bfloat16_rn(v.x), h1 = __float2bfloat16_rn(v.y);
    __nv_bfloat16 h2 = __float2bfloat16_rn(v.z), h3 = __float2bfloat16_rn(v.w);
    __nv_bfloat162* ph = (__nv_bfloat162*)(g_Ah + i4);
    ph[0] = __nv_bfloat162(h0v, h1);
    ph[1] = __nv_bfloat162(h2, h3);
    __nv_bfloat162* pl = (__nv_bfloat162*)(g_Al + i4);
    pl[0] = __nv_bfloat162(__float2bfloat16_rn(v.x - __bfloat162float(h0v)),
                           __float2bfloat16_rn(v.y - __bfloat162float(h1)));
    pl[1] = __nv_bfloat162(__float2bfloat16_rn(v.z - __bfloat162float(h2)),
                           __float2bfloat16_rn(v.w - __bfloat162float(h3)));
}

// Gate permutation matched to the mma.sync C-fragment layout:
// n = gate*1024 + d  ->  np = 64*(d>>4) + 16*((d>>2)&3) + 8*(gate>>1) + 2*(d&3) + (gate&1)
__device__ __forceinline__ int n_to_np(int n) {
    int gate = n >> 10, d = n & 1023;
    return ((d >> 4) << 6) | (((d >> 2) & 3) << 4) | ((gate >> 1) << 3)
           | ((d & 3) << 1) | (gate & 1);
}

// U part (k < 1024): 32x32 tile transpose so both read and write are coalesced.
__global__ void pack_BU(const float* __restrict__ U) {
    __shared__ float tile[32][33];
    int k0 = blockIdx.x * 32, n0 = blockIdx.y * 32;
#pragma unroll
    for (int j = threadIdx.y; j < 32; j += 8)
        tile[j][threadIdx.x] = U[(size_t)(k0 + j) * NROWS + n0 + threadIdx.x];
    __syncthreads();
#pragma unroll
    for (int j = threadIdx.y; j < 32; j += 8) {
        int np = n_to_np(n0 + j);
        float v = tile[threadIdx.x][j];
        __nv_bfloat16 hi = __float2bfloat16_rn(v);
        size_t o = (size_t)np * KTOT + k0 + threadIdx.x;
        g_Bh[o] = hi;
        g_Bl[o] = __float2bfloat16_rn(v - __bfloat162float(hi));
    }
}

// W part (k >= 1024): W[n][k-1024] is already k-contiguous.
__global__ void pack_BW(const float* __restrict__ W) {
    size_t i = (size_t)blockIdx.x * blockDim.x + threadIdx.x;
    int kw = (int)(i & (DH - 1));
    int np = (int)(i >> 10);
    int g = ((np >> 3) & 1) * 2 + (np & 1);
    int d = ((np >> 6) << 4) + (((np >> 4) & 3) << 2) + ((np >> 1) & 3);
    int n = g * DH + d;
    float v = W[(size_t)n * DH + kw];
    __nv_bfloat16 hi = __float2bfloat16_rn(v);
    size_t o = (size_t)np * KTOT + DI + kw;
    g_Bh[o] = hi;
    g_Bl[o] = __float2bfloat16_rn(v - __bfloat162float(hi));
}

// ---------------------------------------------------------------------------
// Fused GEMM: one K sweep, stage holds {Ah, Al, Bh, Bl}; three products
// (Ah*Bh + Ah*Bl + Al*Bh) accumulate into one set of accumulators.
// ---------------------------------------------------------------------------
__device__ __forceinline__ void load_stage(uint32_t sstage, int kt, int mbase,
                                           int nbase, int tid) {
    int kk = kt * KCH;
    int r = tid >> 2;                      // 0..63
    int c = tid & 3;                       // 16B chunk within 64B row
#pragma unroll
    for (int h = 0; h < 2; h++) {
        int row = r + h * 64;
        size_t ga = (size_t)(mbase + row) * KTOT + kk + c * 8;
        size_t gb = (size_t)(nbase + row) * KTOT + kk + c * 8;
        uint32_t so = row * ROWB + c * 16;
        cp_async16(sstage + so,          g_Ah + ga);
        cp_async16(sstage + OFF_AL + so, g_Al + ga);
        cp_async16(sstage + OFF_BH + so, g_Bh + gb);
        cp_async16(sstage + OFF_BL + so, g_Bl + gb);
    }
    CP_COMMIT();
}

__global__ void __launch_bounds__(THREADS)
lstm_gemm(const float* __restrict__ c0, float* __restrict__ outh,
          float* __restrict__ outc) {
    extern __shared__ char smem[];
    uint32_t sbase = smem_u32(smem);
    int tid  = threadIdx.x;
    int lane = tid & 31, wid = tid >> 5;
    int wm = wid & 3, wn = wid >> 2;        // warp grid 4 (m) x 2 (n)
    int mbase = blockIdx.y * TM;
    int nbase = blockIdx.x * TN;

    // Per-lane ldmatrix offsets within an operand tile
    uint32_t aoff = (uint32_t)(wm * 32 + (lane & 7) + ((lane >> 3) & 1) * 8) * ROWB
                    + ((lane >> 4) & 1) * 16;
    uint32_t boff = (uint32_t)(wn * 64 + (lane & 7) + ((lane >> 4) & 1) * 8) * ROWB
                    + ((lane >> 3) & 1) * 16;

    float acc[2][8][4];
#pragma unroll
    for (int mt = 0; mt < 2; mt++)
#pragma unroll
        for (int ng = 0; ng < 8; ng++)
#pragma unroll
            for (int j = 0; j < 4; j++) acc[mt][ng][j] = 0.0f;

    for (int kt = 0; kt < STAGES - 1; kt++)
        load_stage(sbase + (kt & 3) * STAGE_BYTES, kt, mbase, nbase, tid);

#pragma unroll 1
    for (int kt = 0; kt < NKT; kt++) {
        CP_WAIT2();
        __syncthreads();

        int ktl = kt + STAGES - 1;
        if (ktl < NKT)
            load_stage(sbase + (ktl & 3) * STAGE_BYTES, ktl, mbase, nbase, tid);
        else
            CP_COMMIT();   // keep group count uniform for CP_WAIT2

        uint32_t sa = sbase + (kt & 3) * STAGE_BYTES;
#pragma unroll
        for (int ks = 0; ks < 2; ks++) {
            uint32_t a0h[4], a1h[4], a0l[4], a1l[4];
            LDSM_X4(a0h, sa + aoff + ks * 32);
            LDSM_X4(a1h, sa + aoff + 16 * ROWB + ks * 32);
            LDSM_X4(a0l, sa + OFF_AL + aoff + ks * 32);
            LDSM_X4(a1l, sa + OFF_AL + aoff + 16 * ROWB + ks * 32);
            uint32_t bh[8][2], bl[8][2];
#pragma unroll
            for (int gp = 0; gp < 4; gp++) {
                uint32_t t[4];
                LDSM_X4(t, sa + OFF_BH + boff + gp * 16 * ROWB + ks * 32);
                bh[2 * gp][0] = t[0]; bh[2 * gp][1] = t[1];
                bh[2 * gp + 1][0] = t[2]; bh[2 * gp + 1][1] = t[3];
                uint32_t u[4];
                LDSM_X4(u, sa + OFF_BL + boff + gp * 16 * ROWB + ks * 32);
                bl[2 * gp][0] = u[0]; bl[2 * gp][1] = u[1];
                bl[2 * gp + 1][0] = u[2]; bl[2 * gp + 1][1] = u[3];
            }
#pragma unroll
            for (int ng = 0; ng < 8; ng++) {
                MMA16816(acc[0][ng], a0h, bh[ng][0], bh[ng][1]);
                MMA16816(acc[1][ng], a1h, bh[ng][0], bh[ng][1]);
                MMA16816(acc[0][ng], a0h, bl[ng][0], bl[ng][1]);
                MMA16816(acc[1][ng], a1h, bl[ng][0], bl[ng][1]);
                MMA16816(acc[0][ng], a0l, bh[ng][0], bh[ng][1]);
                MMA16816(acc[1][ng], a1l, bh[ng][0], bh[ng][1]);
            }
        }
    }

    // ---- Fused LSTM epilogue (gates land per-thread via B permutation) ----
    int q = lane & 3;
    int wbg = blockIdx.x * 2 + wn;
#pragma unroll
    for (int mt = 0; mt < 2; mt++) {
#pragma unroll
        for (int e = 0; e < 4; e++) {
#pragma unroll
            for (int rs = 0; rs < 2; rs++) {
                float gi = sigf(acc[mt][2 * e][rs * 2 + 0]);
                float gf = sigf(acc[mt][2 * e][rs * 2 + 1]);
                float gg = tanh_f(acc[mt][2 * e + 1][rs * 2 + 0]);
                float go = sigf(acc[mt][2 * e + 1][rs * 2 + 1]);
                int m = mbase + wm * 32 + mt * 16 + (lane >> 2) + rs * 8;
                int d = wbg * 16 + e * 4 + q;
                size_t idx = (size_t)m * DH + d;
                float c0v = __ldg(&c0[idx]);
                float cn = gf * c0v + gi * gg;
                float hn = go * tanh_f(cn);
                outh[idx] = hn;
                outc[idx] = cn;
            }
        }
    }
}

// ---------------------------------------------------------------------------
// Launch
// ---------------------------------------------------------------------------
extern "C" void kernel_launch(void* const* d_in, const int* in_sizes, int n_in,
                              void* d_out, int out_size) {
    const float* X  = (const float*)d_in[0];
    const float* h0 = (const float*)d_in[1];
    const float* c0 = (const float*)d_in[2];
    const float* U  = (const float*)d_in[3];
    const float* W  = (const float*)d_in[4];
    float* outh = (float*)d_out;
    float* outc = outh + (size_t)BB * DH;

    pack_A<<<(BB * KTOT / 4) / 256, 256>>>(X, h0);
    dim3 gbu(DI / 32, NROWS / 32);
    pack_BU<<<gbu, dim3(32, 8)>>>(U);
    pack_BW<<<(NROWS * DH) / 256, 256>>>(W);

    cudaFuncSetAttribute(lstm_gemm, cudaFuncAttributeMaxDynamicSharedMemorySize,
                         SMEM_TOTAL);
    dim3 grid(NROWS / TN, BB / TM);
    lstm_gemm<<<grid, THREADS, SMEM_TOTAL>>>(c0, outh, outc);
}

// round 6
// speedup vs baseline: 1.2959x; 1.2959x over previous
#include <cuda_runtime.h>
#include <cuda_bf16.h>
#include <stdint.h>

// ---------------------------------------------------------------------------
// Problem constants
// ---------------------------------------------------------------------------
#define BB     16384
#define DI     1024
#define DH     1024
#define KTOT   2048           // Di + Dh packed K
#define NROWS  4096           // 4*Dh gate rows (permuted)
#define TM     128
#define TN     128
#define KCH    32             // K elems per pipeline chunk
#define STAGES 2
#define THREADS 256
#define NKT    64             // single fused sweep: 2048/32
#define ROWB   80             // smem row stride bytes (32 bf16 = 64B + 16B pad)
#define TILE_BYTES  (128 * ROWB)              // 10240 per operand tile
#define STAGE_BYTES (4 * TILE_BYTES)          // Ah, Al, Bh, Bl
#define OFF_AL      (1 * TILE_BYTES)
#define OFF_BH      (2 * TILE_BYTES)
#define OFF_BL      (3 * TILE_BYTES)
#define SMEM_TOTAL  (STAGES * STAGE_BYTES)    // 81920 -> 2 CTAs/SM

// ---------------------------------------------------------------------------
// Device scratch
// ---------------------------------------------------------------------------
__device__ __nv_bfloat16 g_Ah[(size_t)BB * KTOT];
__device__ __nv_bfloat16 g_Al[(size_t)BB * KTOT];
__device__ __nv_bfloat16 g_Bh[(size_t)NROWS * KTOT];
__device__ __nv_bfloat16 g_Bl[(size_t)NROWS * KTOT];

// ---------------------------------------------------------------------------
// PTX helpers (base-ISA only)
// ---------------------------------------------------------------------------
__device__ __forceinline__ uint32_t smem_u32(const void* p) {
    uint32_t a;
    asm("{ .reg .u64 t; cvta.to.shared.u64 t, %1; cvt.u32.u64 %0, t; }"
        : "=r"(a) : "l"(p));
    return a;
}

__device__ __forceinline__ void cp_async16(uint32_t so, const void* gp) {
    asm volatile("cp.async.cg.shared.global [%0], [%1], 16;" :: "r"(so), "l"(gp));
}
#define CP_COMMIT() asm volatile("cp.async.commit_group;" ::: "memory")
#define CP_WAIT0()  asm volatile("cp.async.wait_group 0;" ::: "memory")

#define LDSM_X4(R, ADDR)                                                      \
    asm volatile("ldmatrix.sync.aligned.m8n8.x4.shared.b16 {%0,%1,%2,%3}, [%4];" \
                 : "=r"((R)[0]), "=r"((R)[1]), "=r"((R)[2]), "=r"((R)[3])     \
                 : "r"(ADDR))

#define MMA16816(C, A, B0, B1)                                                \
    asm volatile("mma.sync.aligned.m16n8k16.row.col.f32.bf16.bf16.f32 "       \
                 "{%0,%1,%2,%3},{%4,%5,%6,%7},{%8,%9},{%0,%1,%2,%3};"         \
                 : "+f"((C)[0]), "+f"((C)[1]), "+f"((C)[2]), "+f"((C)[3])     \
                 : "r"((A)[0]), "r"((A)[1]), "r"((A)[2]), "r"((A)[3]),        \
                   "r"(B0), "r"(B1))

__device__ __forceinline__ float sigf(float x)   { return 1.0f / (1.0f + __expf(-x)); }
__device__ __forceinline__ float tanh_f(float x) { return 1.0f - 2.0f / (__expf(2.0f * x) + 1.0f); }

// ---------------------------------------------------------------------------
// Prep: pack fp32 inputs into bf16 hi/lo operands
// ---------------------------------------------------------------------------
__global__ void pack_A(const float* __restrict__ X, const float* __restrict__ h0) {
    size_t i4 = ((size_t)blockIdx.x * blockDim.x + threadIdx.x) * 4;
    int k = (int)(i4 & (KTOT - 1));
    size_t b = i4 >> 11;
    const float* src = (k < DI) ? (X + b * DI + k) : (h0 + b * DH + (k - DI));
    float4 v = *(const float4*)src;
    __nv_bfloat16 h0v = __float2bfloat16_rn(v.x), h1 = __float2bfloat16_rn(v.y);
    __nv_bfloat16 h2 = __float2bfloat16_rn(v.z), h3 = __float2bfloat16_rn(v.w);
    __nv_bfloat162* ph = (__nv_bfloat162*)(g_Ah + i4);
    ph[0] = __nv_bfloat162(h0v, h1);
    ph[1] = __nv_bfloat162(h2, h3);
    __nv_bfloat162* pl = (__nv_bfloat162*)(g_Al + i4);
    pl[0] = __nv_bfloat162(__float2bfloat16_rn(v.x - __bfloat162float(h0v)),
                           __float2bfloat16_rn(v.y - __bfloat162float(h1)));
    pl[1] = __nv_bfloat162(__float2bfloat16_rn(v.z - __bfloat162float(h2)),
                           __float2bfloat16_rn(v.w - __bfloat162float(h3)));
}

// Gate permutation matched to the mma.sync C-fragment layout:
// n = gate*1024 + d  ->  np = 64*(d>>4) + 16*((d>>2)&3) + 8*(gate>>1) + 2*(d&3) + (gate&1)
__device__ __forceinline__ int n_to_np(int n) {
    int gate = n >> 10, d = n & 1023;
    return ((d >> 4) << 6) | (((d >> 2) & 3) << 4) | ((gate >> 1) << 3)
           | ((d & 3) << 1) | (gate & 1);
}

// U part (k < 1024): 32x32 tile transpose so both read and write are coalesced.
__global__ void pack_BU(const float* __restrict__ U) {
    __shared__ float tile[32][33];
    int k0 = blockIdx.x * 32, n0 = blockIdx.y * 32;
#pragma unroll
    for (int j = threadIdx.y; j < 32; j += 8)
        tile[j][threadIdx.x] = U[(size_t)(k0 + j) * NROWS + n0 + threadIdx.x];
    __syncthreads();
#pragma unroll
    for (int j = threadIdx.y; j < 32; j += 8) {
        int np = n_to_np(n0 + j);
        float v = tile[threadIdx.x][j];
        __nv_bfloat16 hi = __float2bfloat16_rn(v);
        size_t o = (size_t)np * KTOT + k0 + threadIdx.x;
        g_Bh[o] = hi;
        g_Bl[o] = __float2bfloat16_rn(v - __bfloat162float(hi));
    }
}

// W part (k >= 1024): W[n][k-1024] is already k-contiguous.
__global__ void pack_BW(const float* __restrict__ W) {
    size_t i = (size_t)blockIdx.x * blockDim.x + threadIdx.x;
    int kw = (int)(i & (DH - 1));
    int np = (int)(i >> 10);
    int g = ((np >> 3) & 1) * 2 + (np & 1);
    int d = ((np >> 6) << 4) + (((np >> 4) & 3) << 2) + ((np >> 1) & 3);
    int n = g * DH + d;
    float v = W[(size_t)n * DH + kw];
    __nv_bfloat16 hi = __float2bfloat16_rn(v);
    size_t o = (size_t)np * KTOT + DI + kw;
    g_Bh[o] = hi;
    g_Bl[o] = __float2bfloat16_rn(v - __bfloat162float(hi));
}

// ---------------------------------------------------------------------------
// Fused GEMM: one K sweep, stage holds {Ah, Al, Bh, Bl}; three products
// (Ah*Bh + Ah*Bl + Al*Bh) accumulate into one set of accumulators.
// 2-stage double buffer, 2 CTAs/SM for latency hiding.
// ---------------------------------------------------------------------------
__device__ __forceinline__ void load_stage(uint32_t sstage, int kt, int mbase,
                                           int nbase, int tid) {
    int kk = kt * KCH;
    int r = tid >> 2;                      // 0..63
    int c = tid & 3;                       // 16B chunk within 64B row
#pragma unroll
    for (int h = 0; h < 2; h++) {
        int row = r + h * 64;
        size_t ga = (size_t)(mbase + row) * KTOT + kk + c * 8;
        size_t gb = (size_t)(nbase + row) * KTOT + kk + c * 8;
        uint32_t so = row * ROWB + c * 16;
        cp_async16(sstage + so,          g_Ah + ga);
        cp_async16(sstage + OFF_AL + so, g_Al + ga);
        cp_async16(sstage + OFF_BH + so, g_Bh + gb);
        cp_async16(sstage + OFF_BL + so, g_Bl + gb);
    }
    CP_COMMIT();
}

__global__ void __launch_bounds__(THREADS, 2)
lstm_gemm(const float* __restrict__ c0, float* __restrict__ outh,
          float* __restrict__ outc) {
    extern __shared__ char smem[];
    uint32_t sbase = smem_u32(smem);
    int tid  = threadIdx.x;
    int lane = tid & 31, wid = tid >> 5;
    int wm = wid & 3, wn = wid >> 2;        // warp grid 4 (m) x 2 (n)
    int mbase = blockIdx.y * TM;
    int nbase = blockIdx.x * TN;

    // Per-lane ldmatrix offsets within an operand tile
    uint32_t aoff = (uint32_t)(wm * 32 + (lane & 7) + ((lane >> 3) & 1) * 8) * ROWB
                    + ((lane >> 4) & 1) * 16;
    uint32_t boff = (uint32_t)(wn * 64 + (lane & 7) + ((lane >> 4) & 1) * 8) * ROWB
                    + ((lane >> 3) & 1) * 16;

    float acc[2][8][4];
#pragma unroll
    for (int mt = 0; mt < 2; mt++)
#pragma unroll
        for (int ng = 0; ng < 8; ng++)
#pragma unroll
            for (int j = 0; j < 4; j++) acc[mt][ng][j] = 0.0f;

    load_stage(sbase, 0, mbase, nbase, tid);

#pragma unroll 1
    for (int kt = 0; kt < NKT; kt++) {
        CP_WAIT0();            // stage kt&1 data resident
        __syncthreads();       // everyone done reading the other stage

        if (kt + 1 < NKT)      // prefetch overlaps this iteration's compute
            load_stage(sbase + ((kt + 1) & 1) * STAGE_BYTES, kt + 1, mbase, nbase, tid);

        uint32_t sa = sbase + (kt & 1) * STAGE_BYTES;
#pragma unroll
        for (int ks = 0; ks < 2; ks++) {
            uint32_t a0h[4], a1h[4], a0l[4], a1l[4];
            LDSM_X4(a0h, sa + aoff + ks * 32);
            LDSM_X4(a1h, sa + aoff + 16 * ROWB + ks * 32);
            LDSM_X4(a0l, sa + OFF_AL + aoff + ks * 32);
            LDSM_X4(a1l, sa + OFF_AL + aoff + 16 * ROWB + ks * 32);
#pragma unroll
            for (int gp = 0; gp < 4; gp++) {
                uint32_t bh[4], bl[4];
                LDSM_X4(bh, sa + OFF_BH + boff + gp * 16 * ROWB + ks * 32);
                LDSM_X4(bl, sa + OFF_BL + boff + gp * 16 * ROWB + ks * 32);
                // ng = 2*gp uses (bh[0],bh[1]) / (bl[0],bl[1]);
                // ng = 2*gp+1 uses (bh[2],bh[3]) / (bl[2],bl[3])
                MMA16816(acc[0][2 * gp],     a0h, bh[0], bh[1]);
                MMA16816(acc[1][2 * gp],     a1h, bh[0], bh[1]);
                MMA16816(acc[0][2 * gp + 1], a0h, bh[2], bh[3]);
                MMA16816(acc[1][2 * gp + 1], a1h, bh[2], bh[3]);
                MMA16816(acc[0][2 * gp],     a0h, bl[0], bl[1]);
                MMA16816(acc[1][2 * gp],     a1h, bl[0], bl[1]);
                MMA16816(acc[0][2 * gp + 1], a0h, bl[2], bl[3]);
                MMA16816(acc[1][2 * gp + 1], a1h, bl[2], bl[3]);
                MMA16816(acc[0][2 * gp],     a0l, bh[0], bh[1]);
                MMA16816(acc[1][2 * gp],     a1l, bh[0], bh[1]);
                MMA16816(acc[0][2 * gp + 1], a0l, bh[2], bh[3]);
                MMA16816(acc[1][2 * gp + 1], a1l, bh[2], bh[3]);
            }
        }
    }

    // ---- Fused LSTM epilogue (gates land per-thread via B permutation) ----
    int q = lane & 3;
    int wbg = blockIdx.x * 2 + wn;
#pragma unroll
    for (int mt = 0; mt < 2; mt++) {
#pragma unroll
        for (int e = 0; e < 4; e++) {
#pragma unroll
            for (int rs = 0; rs < 2; rs++) {
                float gi = sigf(acc[mt][2 * e][rs * 2 + 0]);
                float gf = sigf(acc[mt][2 * e][rs * 2 + 1]);
                float gg = tanh_f(acc[mt][2 * e + 1][rs * 2 + 0]);
                float go = sigf(acc[mt][2 * e + 1][rs * 2 + 1]);
                int m = mbase + wm * 32 + mt * 16 + (lane >> 2) + rs * 8;
                int d = wbg * 16 + e * 4 + q;
                size_t idx = (size_t)m * DH + d;
                float c0v = __ldg(&c0[idx]);
                float cn = gf * c0v + gi * gg;
                float hn = go * tanh_f(cn);
                outh[idx] = hn;
                outc[idx] = cn;
            }
        }
    }
}

// ---------------------------------------------------------------------------
// Launch
// ---------------------------------------------------------------------------
extern "C" void kernel_launch(void* const* d_in, const int* in_sizes, int n_in,
                              void* d_out, int out_size) {
    const float* X  = (const float*)d_in[0];
    const float* h0 = (const float*)d_in[1];
    const float* c0 = (const float*)d_in[2];
    const float* U  = (const float*)d_in[3];
    const float* W  = (const float*)d_in[4];
    float* outh = (float*)d_out;
    float* outc = outh + (size_t)BB * DH;

    pack_A<<<(BB * KTOT / 4) / 256, 256>>>(X, h0);
    dim3 gbu(DI / 32, NROWS / 32);
    pack_BU<<<gbu, dim3(32, 8)>>>(U);
    pack_BW<<<(NROWS * DH) / 256, 256>>>(W);

    cudaFuncSetAttribute(lstm_gemm, cudaFuncAttributeMaxDynamicSharedMemorySize,
                         SMEM_TOTAL);
    dim3 grid(NROWS / TN, BB / TM);
    lstm_gemm<<<grid, THREADS, SMEM_TOTAL>>>(c0, outh, outc);
}